// round 1
// baseline (speedup 1.0000x reference)
#include <cuda_runtime.h>
#include <cstdint>

// ---------------- problem constants ----------------
#define TOTAL   340704u        // 16224 + 64896 + 259584 candidates
#define OFF1    16224u
#define OFF2    81120u
#define KSEL    512u
#define NBOX    1536
#define NWORD   24             // 1536/64 mask words per row

// ---------------- device scratch (static, allocation-free) ----------------
__device__ uint32_t            g_keys[TOTAL];
__device__ uint32_t            g_hist [3*65536];
__device__ uint32_t            g_hist2[3*65536];
__device__ uint32_t            g_validCount[3];
__device__ uint32_t            g_binB[3];
__device__ uint32_t            g_countAboveB[3];
__device__ uint32_t            g_threshKey[3];
__device__ uint32_t            g_needEq[3];
__device__ uint32_t            g_selCount[3];
__device__ uint32_t            g_eqCount[3];
__device__ unsigned long long  g_sel[3*512];
__device__ uint32_t            g_eq[3*262144];
__device__ unsigned long long  g_sorted[NBOX];
__device__ float               g_boxes[NBOX*9];
__device__ float               g_nmsb[NBOX*5];      // x1,y1,x2,y2,area
__device__ int                 g_valid[NBOX];
__device__ unsigned long long  g_mask[NBOX*NWORD];

// ---------------- K0: zero per-iteration state ----------------
__global__ void k_zero() {
    uint32_t i = blockIdx.x*blockDim.x + threadIdx.x;
    if (i < 3u*65536u) { g_hist[i] = 0u; g_hist2[i] = 0u; }
    if (i < 3u) { g_validCount[i]=0u; g_selCount[i]=0u; g_eqCount[i]=0u; }
}

// ---------------- K1: scores -> keys + histogram ----------------
__global__ void k_scores(const float* __restrict__ o13,
                         const float* __restrict__ o26,
                         const float* __restrict__ o52) {
    __shared__ uint32_t svc[3];
    if (threadIdx.x < 3) svc[threadIdx.x] = 0u;
    __syncthreads();
    uint32_t i = blockIdx.x*blockDim.x + threadIdx.x;
    if (i < TOTAL) {
        const float* p; uint32_t loc, nhw, hw2; int s;
        if (i < OFF1)      { p=o13; loc=i;      nhw=5408u;  hw2=169u;  s=0; }
        else if (i < OFF2) { p=o26; loc=i-OFF1; nhw=21632u; hw2=676u;  s=1; }
        else               { p=o52; loc=i-OFF2; nhw=86528u; hw2=2704u; s=2; }
        uint32_t a  = loc / nhw, r = loc - a*nhw;
        uint32_t n  = r / hw2,  hw = r - n*hw2;
        float x   = p[(size_t)(n*255u + a*85u)*hw2 + hw];
        float obj = 1.f/(1.f + expf(-x));
        uint32_t key = 0u;
        if (obj > 0.6f) {
            key = __float_as_uint(obj) | 0x80000000u;
            atomicAdd(&g_hist[s*65536 + (key>>16)], 1u);
            atomicAdd(&svc[s], 1u);
        }
        g_keys[i] = key;
    }
    __syncthreads();
    if (threadIdx.x < 3 && svc[threadIdx.x])
        atomicAdd(&g_validCount[threadIdx.x], svc[threadIdx.x]);
}

// ---------------- K2/K4: locate threshold bin / exact key ----------------
__global__ __launch_bounds__(1024) void k_scan(int pass) {
    int s = blockIdx.x;
    int t = threadIdx.x;
    uint32_t K;
    const uint32_t* hist;
    if (pass == 0) {
        if (g_validCount[s] < KSEL) {
            if (t == 0) { g_binB[s]=0xFFFFFFFFu; g_threshKey[s]=0u; g_needEq[s]=0u; }
            return;
        }
        K = KSEL; hist = g_hist + s*65536;
    } else {
        if (g_binB[s] == 0xFFFFFFFFu) return;
        K = KSEL - g_countAboveB[s]; hist = g_hist2 + s*65536;
    }
    __shared__ uint32_t ssum[1024];
    uint32_t base = (uint32_t)t * 64u;
    uint32_t local = 0u;
    for (int k = 0; k < 64; k++) local += hist[base + k];
    ssum[t] = local;
    __syncthreads();
    for (int off = 1; off < 1024; off <<= 1) {      // inclusive suffix scan
        uint32_t add = (t + off < 1024) ? ssum[t + off] : 0u;
        __syncthreads();
        ssum[t] += add;
        __syncthreads();
    }
    uint32_t S = ssum[t];
    uint32_t Snext = (t < 1023) ? ssum[t+1] : 0u;
    if (S >= K && Snext < K) {
        uint32_t cum = Snext;
        for (int k = 63; k >= 0; k--) {
            uint32_t hc = hist[base + k];
            cum += hc;
            if (cum >= K) {
                uint32_t bin = base + (uint32_t)k;
                uint32_t above = cum - hc;
                if (pass == 0) { g_binB[s] = bin; g_countAboveB[s] = above; }
                else { g_threshKey[s] = (g_binB[s] << 16) | bin; g_needEq[s] = K - above; }
                break;
            }
        }
    }
}

// ---------------- K3: second-level histogram ----------------
__global__ void k_hist2() {
    uint32_t i = blockIdx.x*blockDim.x + threadIdx.x;
    if (i >= TOTAL) return;
    int s = (i < OFF1) ? 0 : (i < OFF2) ? 1 : 2;
    uint32_t key = g_keys[i];
    if ((key >> 16) == g_binB[s])
        atomicAdd(&g_hist2[s*65536 + (key & 0xFFFFu)], 1u);
}

// ---------------- K5: compact winners + equal-key pool ----------------
__global__ void k_compact() {
    uint32_t i = blockIdx.x*blockDim.x + threadIdx.x;
    if (i >= TOTAL) return;
    uint32_t s, loc, nhw;
    if (i < OFF1)      { s=0; loc=i;      nhw=5408u;  }
    else if (i < OFF2) { s=1; loc=i-OFF1; nhw=21632u; }
    else               { s=2; loc=i-OFF2; nhw=86528u; }
    uint32_t key = g_keys[i];
    if (key == 0u) return;
    uint32_t tk = g_threshKey[s];
    uint32_t a = loc / nhw, r = loc - a*nhw;
    uint32_t orig = r*3u + a;                     // reference flatten order
    if (key > tk) {
        uint32_t pos = atomicAdd(&g_selCount[s], 1u);
        g_sel[s*512u + pos] = ((unsigned long long)key << 32) | orig;
    } else if (key == tk && g_needEq[s] != 0u) {
        uint32_t pos = atomicAdd(&g_eqCount[s], 1u);
        g_eq[s*262144u + pos] = orig;
    }
}

// ---------------- K6: resolve equal-key ties (lowest index first) ----------------
__global__ void k_ties() {
    int s = blockIdx.x;
    uint32_t need = g_needEq[s];
    if (need == 0u) return;
    uint32_t n  = g_eqCount[s];
    uint32_t tk = g_threshKey[s];
    const uint32_t* eq = &g_eq[s * 262144u];
    __shared__ uint32_t scnt;
    uint32_t T = 0xFFFFFFFFu;
    if (n > need) {                       // binary search need-th smallest index
        uint32_t lo = 0u, hi = 262143u;
        while (lo < hi) {
            uint32_t mid = (lo + hi) >> 1;
            if (threadIdx.x == 0) scnt = 0u;
            __syncthreads();
            uint32_t c = 0u;
            for (uint32_t j = threadIdx.x; j < n; j += blockDim.x)
                if (eq[j] <= mid) c++;
            if (c) atomicAdd(&scnt, c);
            __syncthreads();
            uint32_t total = scnt;
            __syncthreads();
            if (total >= need) hi = mid; else lo = mid + 1u;
        }
        T = lo;
    }
    __syncthreads();
    for (uint32_t j = threadIdx.x; j < n; j += blockDim.x) {
        uint32_t idx = eq[j];
        if (idx <= T) {
            uint32_t pos = atomicAdd(&g_selCount[s], 1u);
            g_sel[s*512u + pos] = ((unsigned long long)tk << 32) | idx;
        }
    }
}

// ---------------- K7: global bitonic sort (score desc, concat-pos asc) ----------------
__global__ __launch_bounds__(1024) void k_sort() {
    __shared__ unsigned long long sm[2048];
    int t = threadIdx.x;
    const uint32_t offc[3] = {0u, OFF1, OFF2};
    for (int j = t; j < 2048; j += 1024) {
        unsigned long long v = 0ull;
        if (j < NBOX) {
            int s = j >> 9, p = j & 511;
            if ((uint32_t)p < g_selCount[s]) {
                unsigned long long e = g_sel[s*512 + p];
                uint32_t key  = (uint32_t)(e >> 32);
                uint32_t gidx = offc[s] + (uint32_t)e;
                v = ((unsigned long long)key << 32) | (uint32_t)(~gidx);
            }
        }
        sm[j] = v;
    }
    __syncthreads();
    for (int k = 2; k <= 2048; k <<= 1)
        for (int j = k >> 1; j > 0; j >>= 1) {
            for (int i = t; i < 2048; i += 1024) {
                int ixj = i ^ j;
                if (ixj > i) {
                    bool desc = ((i & k) == 0);
                    unsigned long long x = sm[i], y = sm[ixj];
                    if (desc ? (x < y) : (x > y)) { sm[i] = y; sm[ixj] = x; }
                }
            }
            __syncthreads();
        }
    for (int j = t; j < NBOX; j += 1024) g_sorted[j] = sm[j];
}

// ---------------- K8: decode winners (one warp per box) ----------------
__global__ void k_decode(const float* __restrict__ o13, const float* __restrict__ o26,
                         const float* __restrict__ o52,
                         const float* __restrict__ a13, const float* __restrict__ a26,
                         const float* __restrict__ a52) {
    int r = (blockIdx.x * blockDim.x + threadIdx.x) >> 5;
    int lane = threadIdx.x & 31;
    if (r >= NBOX) return;
    unsigned long long e = g_sorted[r];
    uint32_t key = (uint32_t)(e >> 32);
    if (key == 0u) {
        if (lane == 0) {
            #pragma unroll
            for (int k = 0; k < 9; k++) g_boxes[r*9+k] = 0.f;
            #pragma unroll
            for (int k = 0; k < 5; k++) g_nmsb[r*5+k] = 0.f;
            g_valid[r] = 0;
        }
        return;
    }
    uint32_t gidx = ~(uint32_t)e;
    const float* p; const float* anc; int H; float ts; uint32_t loc;
    if (gidx < OFF1)      { p=o13; anc=a13; H=13; ts=32.f; loc=gidx; }
    else if (gidx < OFF2) { p=o26; anc=a26; H=26; ts=16.f; loc=gidx-OFF1; }
    else                  { p=o52; anc=a52; H=52; ts=8.f;  loc=gidx-OFF2; }
    uint32_t a = loc % 3u; uint32_t q = loc / 3u;
    uint32_t w = q % (uint32_t)H; q /= (uint32_t)H;
    uint32_t h = q % (uint32_t)H; uint32_t n = q / (uint32_t)H;
    int HW = H*H;
    const float* base = p + (size_t)(n*255u + a*85u)*HW + h*H + w;
    // argmax over 80 classes, first-max tie-break
    float bv = -1e30f; int bc = 1 << 30;
    for (int c = lane; c < 80; c += 32) {
        float v = base[(5 + c) * HW];
        if (v > bv) { bv = v; bc = c; }
    }
    #pragma unroll
    for (int off = 16; off; off >>= 1) {
        float ov = __shfl_down_sync(0xffffffffu, bv, off);
        int   oc = __shfl_down_sync(0xffffffffu, bc, off);
        if (ov > bv || (ov == bv && oc < bc)) { bv = ov; bc = oc; }
    }
    if (lane == 0) {
        float v1 = base[HW], v2 = base[2*HW], v3 = base[3*HW], v4 = base[4*HW];
        float obj = __uint_as_float(key ^ 0x80000000u);
        float cx = ((float)w + v1) * ts / 416.0f;
        float cy = ((float)h + v2) * ts / 416.0f;
        float bw = anc[a*2+0] * expf(v3) / 416.0f;
        float bh = anc[a*2+1] * expf(v4) / 416.0f;
        float* B = &g_boxes[r*9];
        B[0]=(float)n; B[1]=cx; B[2]=cy; B[3]=bw; B[4]=bh;
        B[5]=obj; B[6]=(float)bc; B[7]=(float)h; B[8]=(float)w;
        float x1 = cx - bw*0.5f, y1 = cy - bh*0.5f;
        float x2 = cx + bw*0.5f, y2 = cy + bh*0.5f;
        float area = fmaxf(x2-x1, 0.f) * fmaxf(y2-y1, 0.f);
        float* Nn = &g_nmsb[r*5];
        Nn[0]=x1; Nn[1]=y1; Nn[2]=x2; Nn[3]=y2; Nn[4]=area;
        g_valid[r] = 1;
    }
}

// ---------------- K9: suppression bitmask (iou inter/min > 0.7, col > row) ----------------
__global__ void k_mask() {
    int cb = blockIdx.x, rb = blockIdx.y;
    __shared__ float c0[64], c1[64], c2[64], c3[64], ca[64];
    int t = threadIdx.x;
    int c = cb*64 + t;
    c0[t]=g_nmsb[c*5+0]; c1[t]=g_nmsb[c*5+1]; c2[t]=g_nmsb[c*5+2];
    c3[t]=g_nmsb[c*5+3]; ca[t]=g_nmsb[c*5+4];
    __syncthreads();
    int r = rb*64 + t;
    float x1=g_nmsb[r*5+0], y1=g_nmsb[r*5+1], x2=g_nmsb[r*5+2],
          y2=g_nmsb[r*5+3], ar=g_nmsb[r*5+4];
    unsigned long long bits = 0ull;
    #pragma unroll 4
    for (int j = 0; j < 64; j++) {
        int cc = cb*64 + j;
        if (cc > r) {
            float ix = fmaxf(fminf(x2, c2[j]) - fmaxf(x1, c0[j]), 0.f);
            float iy = fmaxf(fminf(y2, c3[j]) - fmaxf(y1, c1[j]), 0.f);
            float iou = (ix * iy) / fmaxf(fminf(ar, ca[j]), 1e-9f);
            if (iou > 0.7f) bits |= (1ull << j);
        }
    }
    g_mask[r*NWORD + cb] = bits;
}

// ---------------- K10: serial greedy scan + masked output ----------------
__global__ void k_nms_out(float* __restrict__ out) {
    __shared__ unsigned long long tile[64*NWORD];
    __shared__ unsigned char keepArr[NBOX];
    __shared__ unsigned char svalid[NBOX];
    int tid = threadIdx.x;
    for (int i = tid; i < NBOX; i += 256) svalid[i] = (unsigned char)g_valid[i];
    unsigned long long remv_l = 0ull;                 // lanes 0..23 of warp 0
    __syncthreads();
    for (int c = 0; c < NWORD; c++) {
        for (int k = tid; k < 64*NWORD; k += 256)
            tile[k] = g_mask[(size_t)(c*64)*NWORD + k];
        __syncthreads();
        if (tid < 32) {
            unsigned long long cur = __shfl_sync(0xffffffffu, remv_l, c);
            unsigned long long keptbits = 0ull;
            if (tid == 0) {
                for (int j = 0; j < 64; j++) {
                    int i = c*64 + j;
                    bool kept = svalid[i] && !((cur >> j) & 1ull);
                    if (kept) { cur |= tile[j*NWORD + c]; keptbits |= 1ull << j; }
                    keepArr[i] = kept;
                }
            }
            keptbits = __shfl_sync(0xffffffffu, keptbits, 0);
            if (tid < NWORD) {
                unsigned long long acc = 0ull;
                for (int j = 0; j < 64; j++)
                    if ((keptbits >> j) & 1ull) acc |= tile[j*NWORD + tid];
                remv_l |= acc;
            }
        }
        __syncthreads();
    }
    for (int e = tid; e < NBOX*9; e += 256) {
        int r = e / 9;
        out[e] = g_boxes[e] * (keepArr[r] ? 1.f : 0.f);
    }
}

// ---------------- launcher ----------------
extern "C" void kernel_launch(void* const* d_in, const int* in_sizes, int n_in,
                              void* d_out, int out_size) {
    const float* o13 = (const float*)d_in[0];
    const float* o26 = (const float*)d_in[1];
    const float* o52 = (const float*)d_in[2];
    const float* a13 = (const float*)d_in[3];
    const float* a26 = (const float*)d_in[4];
    const float* a52 = (const float*)d_in[5];
    float* out = (float*)d_out;

    int gridAll = (int)((TOTAL + 255u) / 256u);
    k_zero   <<<768, 256>>>();
    k_scores <<<gridAll, 256>>>(o13, o26, o52);
    k_scan   <<<3, 1024>>>(0);
    k_hist2  <<<gridAll, 256>>>();
    k_scan   <<<3, 1024>>>(1);
    k_compact<<<gridAll, 256>>>();
    k_ties   <<<3, 256>>>();
    k_sort   <<<1, 1024>>>();
    k_decode <<<192, 256>>>(o13, o26, o52, a13, a26, a52);
    k_mask   <<<dim3(24,24), 64>>>();
    k_nms_out<<<1, 256>>>(out);
    (void)in_sizes; (void)n_in; (void)out_size;
}